// round 2
// baseline (speedup 1.0000x reference)
#include <cuda_runtime.h>

// Problem shape (fixed): z_hat [B,T,D] f32, P [B,T] f32, lengths [B] i32 -> out [B,T,D] f32
#define BB 4
#define TT 4096
#define DD 512
#define CC 256          // number of chunks along T
#define LL 16           // chunk length, TT/CC
#define D4 (DD/4)       // float4 lanes per row (128)

// Scratch (allocation-free rule: __device__ globals)
__device__ float g_Bsum[BB * CC * DD];   // per-chunk zero-init scan result (carry vector)
__device__ float g_A[BB * CC];           // per-chunk product of q
__device__ float g_Zinit[BB * CC * DD];  // exclusive prefix state entering each chunk

// ---------------------------------------------------------------------------
// K1: per-chunk summaries.
//   Bsum[b,c,d] = sum_{k=0..L-1} w[k] * x[b, c*L+k, d],
//   w[k] = Peff[c*L+k] * prod_{j=k+1..L-1} q[c*L+j],   A[b,c] = prod q over chunk
// Pure weighted reduction -> no serial chain, high MLP. Skips fully-masked chunks.
// ---------------------------------------------------------------------------
__global__ void __launch_bounds__(128) k1_chunk_summary(
    const float* __restrict__ z, const float* __restrict__ P,
    const int* __restrict__ lengths)
{
    const int c = blockIdx.x;
    const int b = blockIdx.y;
    const int len = lengths[b];
    if (c * LL >= len) return;  // output of all later chunks is masked; state unused

    __shared__ float sw[LL];
    __shared__ float sq[LL], sp[LL];
    const int tid = threadIdx.x;  // 0..127 (one float4 of D each)

    if (tid < LL) {
        float p = P[b * TT + c * LL + tid];
        p = fminf(fmaxf(p, 0.0f), 1.0f - 1e-6f);
        sq[tid] = 1.0f - p;
        sp[tid] = fmaxf(p, 1e-6f);
    }
    __syncthreads();
    if (tid == 0) {
        float r = 1.0f;
#pragma unroll
        for (int k = LL - 1; k >= 0; --k) { sw[k] = sp[k] * r; r *= sq[k]; }
        g_A[b * CC + c] = r;
    }
    __syncthreads();

    const float4* __restrict__ zp =
        (const float4*)(z + ((size_t)b * TT + (size_t)c * LL) * DD);

    float4 acc = make_float4(0.f, 0.f, 0.f, 0.f);
#pragma unroll
    for (int k = 0; k < LL; ++k) {
        float4 x = zp[(size_t)k * D4 + tid];
        float w = sw[k];
        acc.x = fmaf(w, x.x, acc.x);
        acc.y = fmaf(w, x.y, acc.y);
        acc.z = fmaf(w, x.z, acc.z);
        acc.w = fmaf(w, x.w, acc.w);
    }
    ((float4*)g_Bsum)[(size_t)(b * CC + c) * D4 + tid] = acc;
}

// ---------------------------------------------------------------------------
// K2: serial combine across chunks (tiny).
//   Zinit[b,0,d] = 0;  Zinit[b,c,d] = A[b,c-1]*Zinit[b,c-1,d] + Bsum[b,c-1,d]
// Only walks active chunks (c*LL < len).
// ---------------------------------------------------------------------------
__global__ void __launch_bounds__(128) k2_combine(const int* __restrict__ lengths)
{
    const int b = blockIdx.x;
    const int tid = threadIdx.x;  // 128 threads, float4 each
    const int len = lengths[b];
    const int cmax = (len + LL - 1) / LL;  // chunks whose output is (partly) live

    float4 zv = make_float4(0.f, 0.f, 0.f, 0.f);
    const float4* __restrict__ bs = (const float4*)g_Bsum;
    float4* __restrict__ zi = (float4*)g_Zinit;
#pragma unroll 4
    for (int c = 0; c < cmax; ++c) {
        zi[(size_t)(b * CC + c) * D4 + tid] = zv;
        float a = g_A[b * CC + c];
        float4 s = bs[(size_t)(b * CC + c) * D4 + tid];
        zv.x = fmaf(a, zv.x, s.x);
        zv.y = fmaf(a, zv.y, s.y);
        zv.z = fmaf(a, zv.z, s.z);
        zv.w = fmaf(a, zv.w, s.w);
    }
}

// ---------------------------------------------------------------------------
// K3: per-chunk local scan seeded with Zinit; mask by lengths; write output.
// Chain is only LL*~8 cycles per thread. Fully-masked chunks write zeros, no loads.
// ---------------------------------------------------------------------------
__global__ void __launch_bounds__(128) k3_scan_out(
    const float* __restrict__ z, const float* __restrict__ P,
    const int* __restrict__ lengths, float* __restrict__ out)
{
    const int c = blockIdx.x;
    const int b = blockIdx.y;
    const int tid = threadIdx.x;
    const int len = lengths[b];
    const int t0 = c * LL;

    float4* __restrict__ op = (float4*)(out + ((size_t)b * TT + (size_t)t0) * DD);

    if (t0 >= len) {
        // entire chunk masked: write zeros (d_out is poisoned), no loads needed
        float4 zero = make_float4(0.f, 0.f, 0.f, 0.f);
#pragma unroll
        for (int k = 0; k < LL; ++k) op[(size_t)k * D4 + tid] = zero;
        return;
    }

    __shared__ float sq[LL], sp[LL];
    if (tid < LL) {
        float p = P[b * TT + t0 + tid];
        p = fminf(fmaxf(p, 0.0f), 1.0f - 1e-6f);
        sq[tid] = 1.0f - p;
        sp[tid] = fmaxf(p, 1e-6f);
    }
    __syncthreads();

    float4 zv = ((const float4*)g_Zinit)[(size_t)(b * CC + c) * D4 + tid];
    const float4* __restrict__ zp =
        (const float4*)(z + ((size_t)b * TT + (size_t)t0) * DD);

#pragma unroll
    for (int k = 0; k < LL; ++k) {
        float4 x = zp[(size_t)k * D4 + tid];
        float q = sq[k], p = sp[k];
        zv.x = fmaf(q, zv.x, p * x.x);
        zv.y = fmaf(q, zv.y, p * x.y);
        zv.z = fmaf(q, zv.z, p * x.z);
        zv.w = fmaf(q, zv.w, p * x.w);
        float m = (t0 + k < len) ? 1.0f : 0.0f;
        float4 o = make_float4(zv.x * m, zv.y * m, zv.z * m, zv.w * m);
        op[(size_t)k * D4 + tid] = o;
    }
}

extern "C" void kernel_launch(void* const* d_in, const int* in_sizes, int n_in,
                              void* d_out, int out_size)
{
    const float* z = (const float*)d_in[0];       // z_hat [B,T,D]
    const float* P = (const float*)d_in[1];       // P     [B,T]
    const int* lengths = (const int*)d_in[2];     // lengths [B]
    float* out = (float*)d_out;                   // [B,T,D] f32

    dim3 grid(CC, BB);
    k1_chunk_summary<<<grid, 128>>>(z, P, lengths);
    k2_combine<<<BB, 128>>>(lengths);
    k3_scan_out<<<grid, 128>>>(z, P, lengths, out);
}

// round 3
// speedup vs baseline: 2.3667x; 2.3667x over previous
#include <cuda_runtime.h>

// Problem shape (fixed): z_hat [B,T,D] f32, P [B,T] f32, lengths [B] i32 -> out [B,T,D] f32
#define BB 4
#define TT 4096
#define DD 512
#define CC 256          // number of chunks along T
#define LL 16           // chunk length, TT/CC
#define HALF 8          // rows per thread-half (LL/2)
#define D4 (DD/4)       // float4 lanes per row (128)
#define PF 8            // K2 prefetch depth

// Scratch (allocation-free rule: __device__ globals)
__device__ float g_Bsum[BB * CC * DD];   // per-chunk zero-init scan result (carry vector)
__device__ float g_A[BB * CC];           // per-chunk product of q
__device__ float g_Zinit[BB * CC * DD];  // exclusive prefix state entering each chunk

// ---------------------------------------------------------------------------
// K1: per-chunk summaries, chunk split across 2 thread-halves for 2x warps.
//   Per half: acc_h = sum_k p[k]*(prod_{j>k in half} q[j])*x[k],  r_h = prod q
//   Combine (half1 = later rows):  Bsum = acc1 + r1*acc0,  A = r1*r0
// ---------------------------------------------------------------------------
__global__ void __launch_bounds__(256) k1_chunk_summary(
    const float* __restrict__ z, const float* __restrict__ P,
    const int* __restrict__ lengths)
{
    const int c = blockIdx.x;
    const int b = blockIdx.y;
    const int len = lengths[b];
    if (c * LL >= len) return;  // masked chunk: state never consumed

    const int lane = threadIdx.x;  // 0..127 (float4 lane over D)
    const int h = threadIdx.y;     // 0..1 (chunk half)

    __shared__ float sp[LL], sq[LL];
    __shared__ float4 sacc[D4];
    __shared__ float sr0;

    const int t = h * 128 + lane;
    if (t < LL) {
        float p = P[b * TT + c * LL + t];
        p = fminf(fmaxf(p, 0.0f), 1.0f - 1e-6f);
        sq[t] = 1.0f - p;
        sp[t] = fmaxf(p, 1e-6f);
    }
    __syncthreads();

    const float4* __restrict__ zp =
        (const float4*)(z + ((size_t)b * TT + (size_t)c * LL + h * HALF) * DD);

    float r = 1.0f;
    float4 acc = make_float4(0.f, 0.f, 0.f, 0.f);
#pragma unroll
    for (int k = HALF - 1; k >= 0; --k) {   // backward: w[k] = p[k]*prod_{j>k} q[j]
        float4 x = zp[(size_t)k * D4 + lane];
        const int kk = h * HALF + k;
        float w = sp[kk] * r;
        acc.x = fmaf(w, x.x, acc.x);
        acc.y = fmaf(w, x.y, acc.y);
        acc.z = fmaf(w, x.z, acc.z);
        acc.w = fmaf(w, x.w, acc.w);
        r *= sq[kk];
    }

    if (h == 0) {
        sacc[lane] = acc;
        if (lane == 0) sr0 = r;
    }
    __syncthreads();
    if (h == 1) {
        float4 a0 = sacc[lane];
        acc.x = fmaf(r, a0.x, acc.x);
        acc.y = fmaf(r, a0.y, acc.y);
        acc.z = fmaf(r, a0.z, acc.z);
        acc.w = fmaf(r, a0.w, acc.w);
        ((float4*)g_Bsum)[(size_t)(b * CC + c) * D4 + lane] = acc;
        if (lane == 0) g_A[b * CC + c] = r * sr0;
    }
}

// ---------------------------------------------------------------------------
// K2: serial combine across chunks, software-pipelined.
//   Zinit[b,0,d]=0; Zinit[b,c,d]=A[b,c-1]*Zinit[b,c-1,d]+Bsum[b,c-1,d]
// Loads (independent of the carry) are prefetched one batch ahead, so the
// dependency chain is just cmax FMAs (~4 cyc each), not cmax L2 round-trips.
// ---------------------------------------------------------------------------
__global__ void __launch_bounds__(128) k2_combine(const int* __restrict__ lengths)
{
    const int b = blockIdx.x;
    const int tid = threadIdx.x;  // float4 lane
    const int len = lengths[b];
    const int cmax = (len + LL - 1) / LL;
    if (cmax == 0) return;

    const float4* __restrict__ bs = (const float4*)g_Bsum;
    float4* __restrict__ zi = (float4*)g_Zinit;

    float4 zv = make_float4(0.f, 0.f, 0.f, 0.f);
    float4 cs[PF];
    float  ca[PF];
#pragma unroll
    for (int j = 0; j < PF; ++j) {
        int idx = min(j, CC - 1);
        cs[j] = bs[(size_t)(b * CC + idx) * D4 + tid];
        ca[j] = g_A[b * CC + idx];
    }

    for (int base = 0; base < cmax; base += PF) {
        float4 ns[PF];
        float  na[PF];
#pragma unroll
        for (int j = 0; j < PF; ++j) {       // prefetch next batch (independent)
            int idx = min(base + PF + j, CC - 1);
            ns[j] = bs[(size_t)(b * CC + idx) * D4 + tid];
            na[j] = g_A[b * CC + idx];
        }
#pragma unroll
        for (int j = 0; j < PF; ++j) {       // consume current batch (serial FMA only)
            if (base + j < cmax) {
                zi[(size_t)(b * CC + base + j) * D4 + tid] = zv;
                zv.x = fmaf(ca[j], zv.x, cs[j].x);
                zv.y = fmaf(ca[j], zv.y, cs[j].y);
                zv.z = fmaf(ca[j], zv.z, cs[j].z);
                zv.w = fmaf(ca[j], zv.w, cs[j].w);
            }
        }
#pragma unroll
        for (int j = 0; j < PF; ++j) { cs[j] = ns[j]; ca[j] = na[j]; }
    }
}

// ---------------------------------------------------------------------------
// K3: per-chunk local scan seeded with Zinit, split across 2 thread-halves.
// Half 1 preloads its x while half 0 scans; smem hands the carry across.
// Fully-masked chunks write zeros with no loads.
// ---------------------------------------------------------------------------
__global__ void __launch_bounds__(256) k3_scan_out(
    const float* __restrict__ z, const float* __restrict__ P,
    const int* __restrict__ lengths, float* __restrict__ out)
{
    const int c = blockIdx.x;
    const int b = blockIdx.y;
    const int lane = threadIdx.x;
    const int h = threadIdx.y;
    const int len = lengths[b];
    const int t0 = c * LL;

    float4* __restrict__ op = (float4*)(out + ((size_t)b * TT + (size_t)t0) * DD);

    if (t0 >= len) {
        float4 zero = make_float4(0.f, 0.f, 0.f, 0.f);
#pragma unroll
        for (int k = 0; k < HALF; ++k)
            op[(size_t)(h * HALF + k) * D4 + lane] = zero;
        return;
    }

    __shared__ float sp[LL], sq[LL];
    __shared__ float4 mid[D4];

    const int t = h * 128 + lane;
    if (t < LL) {
        float p = P[b * TT + t0 + t];
        p = fminf(fmaxf(p, 0.0f), 1.0f - 1e-6f);
        sq[t] = 1.0f - p;
        sp[t] = fmaxf(p, 1e-6f);
    }
    __syncthreads();

    const float4* __restrict__ zp =
        (const float4*)(z + ((size_t)b * TT + (size_t)t0) * DD);

    // preload this half's rows (independent loads, in flight during handoff)
    float4 xr[HALF];
#pragma unroll
    for (int k = 0; k < HALF; ++k)
        xr[k] = zp[(size_t)(h * HALF + k) * D4 + lane];

    float4 zv;
    if (h == 0) {
        zv = ((const float4*)g_Zinit)[(size_t)(b * CC + c) * D4 + lane];
#pragma unroll
        for (int k = 0; k < HALF; ++k) {
            float q = sq[k], p = sp[k];
            zv.x = fmaf(q, zv.x, p * xr[k].x);
            zv.y = fmaf(q, zv.y, p * xr[k].y);
            zv.z = fmaf(q, zv.z, p * xr[k].z);
            zv.w = fmaf(q, zv.w, p * xr[k].w);
            float m = (t0 + k < len) ? 1.0f : 0.0f;
            op[(size_t)k * D4 + lane] =
                make_float4(zv.x * m, zv.y * m, zv.z * m, zv.w * m);
        }
        mid[lane] = zv;
    }
    __syncthreads();
    if (h == 1) {
        zv = mid[lane];
#pragma unroll
        for (int k = 0; k < HALF; ++k) {
            const int kk = HALF + k;
            float q = sq[kk], p = sp[kk];
            zv.x = fmaf(q, zv.x, p * xr[k].x);
            zv.y = fmaf(q, zv.y, p * xr[k].y);
            zv.z = fmaf(q, zv.z, p * xr[k].z);
            zv.w = fmaf(q, zv.w, p * xr[k].w);
            float m = (t0 + kk < len) ? 1.0f : 0.0f;
            op[(size_t)kk * D4 + lane] =
                make_float4(zv.x * m, zv.y * m, zv.z * m, zv.w * m);
        }
    }
}

extern "C" void kernel_launch(void* const* d_in, const int* in_sizes, int n_in,
                              void* d_out, int out_size)
{
    const float* z = (const float*)d_in[0];       // z_hat [B,T,D]
    const float* P = (const float*)d_in[1];       // P     [B,T]
    const int* lengths = (const int*)d_in[2];     // lengths [B]
    float* out = (float*)d_out;                   // [B,T,D] f32

    dim3 grid(CC, BB);
    dim3 blk(128, 2);
    k1_chunk_summary<<<grid, blk>>>(z, P, lengths);
    k2_combine<<<BB, 128>>>(lengths);
    k3_scan_out<<<grid, blk>>>(z, P, lengths, out);
}